// round 11
// baseline (speedup 1.0000x reference)
#include <cuda_runtime.h>
#include <math.h>

#define B_IMGS   64
#define NBLK     4096
#define NLIN     16384
#define NCHR     16384
#define TOPK     100
#define KSEL     128
#define NT       256
#define NQ       4                 // filter CTAs per (b, level)
#define FASTCAP  512
#define NSEG     (B_IMGS * 3)

#define TH0 1.5f                   // threshold guess, N=4096
#define TH1 2.25f                  // threshold guess, N=16384

// Output layout (float32), reference return order (*blk, *lin, *chr):
//  blk_data [64,100,4]  @ 0       blk_scores @ 25600   blk_keep @ 32000
//  lin_data [64,100,4]  @ 38400   lin_scores @ 64000   lin_keep @ 70400
//  chr_data [64,100,16] @ 76800   chr_scores @ 179200  chr_keep @ 185600

__device__ int   g_cnt[NSEG];            // zero at load; finisher re-zeroes each run
__device__ int   g_ticket[NSEG];
__device__ uint2 g_cand[NSEG * FASTCAP];

struct __align__(16) SharedState {
    unsigned int adj[TOPK][4];
    float4 sdat4[TOPK][4];
    float4 sbox4[TOPK];
    unsigned long long fckey[FASTCAP];
    unsigned long long wkeys[8];
    uint2 scand[FASTCAP];
    float sval[TOPK];
    int   sidx[TOPK];
    float sarea[TOPK];
    float sbelong[TOPK];
    int   skeep[TOPK];
    int   klist[TOPK];
    unsigned int keepw[4];
    int totals[32];
    int cnt;
    int cnt_g;
    int kcnt;
    int argmax_idx;
    int is_last;
};

__device__ __forceinline__ unsigned int fkey(float f) {
    unsigned int u = __float_as_uint(f);
    return u ^ (((unsigned int)((int)u >> 31)) | 0x80000000u);
}

__device__ __forceinline__ void l2_prefetch(const void* p) {
    asm volatile("prefetch.global.L2 [%0];" :: "l"(p));
}

__device__ __forceinline__ unsigned long long sig_key(unsigned int key, int idx) {
    unsigned int u = key ^ ((key & 0x80000000u) ? 0x80000000u : 0xFFFFFFFFu);
    float x = __uint_as_float(u);
    float prob = 1.0f / (1.0f + __expf(-x));
    return ((unsigned long long)__float_as_uint(prob) << 32)
           | (unsigned int)(~(unsigned int)idx);
}

// ---- per-quarter streaming filter: QF4 float4 per thread ----
template<int QF4, int LEVEL>
__device__ __forceinline__ void filter_part(
    int b, int quarter, int tid, int seg,
    const float* __restrict__ lb,
    const float* __restrict__ blk_raw,
    const float* __restrict__ lin_raw,
    const float* __restrict__ chr_raw)
{
    constexpr float TH = (LEVEL == 0) ? TH0 : TH1;
    const float4* lb4 = (const float4*)lb + quarter * (QF4 * NT);
    const int ebase0 = quarter * (QF4 * NT * 4);
#pragma unroll
    for (int r4 = 0; r4 < QF4; ++r4) {
        float4 v = lb4[tid + r4 * NT];
        const int base = ebase0 + 4 * (tid + r4 * NT);
        float fv[4] = { v.x, v.y, v.z, v.w };
#pragma unroll
        for (int c = 0; c < 4; ++c) {
            if (fv[c] >= TH) {
                int idx = base + c;
                int p = atomicAdd(&g_cnt[seg], 1);
                if (p < FASTCAP) g_cand[seg * FASTCAP + p] = make_uint2(fkey(fv[c]), (unsigned int)idx);
                if (LEVEL == 0) {
                    l2_prefetch(blk_raw + ((size_t)b * NBLK + (size_t)idx) * 4);
                } else if (LEVEL == 1) {
                    l2_prefetch(lin_raw + ((size_t)b * NLIN + (size_t)idx) * 4);
                    l2_prefetch(blk_raw + ((size_t)b * NBLK + (size_t)(idx >> 2)) * 4);
                } else {
                    l2_prefetch(chr_raw + ((size_t)b * NCHR + (size_t)idx) * 16);
                    l2_prefetch(lin_raw + ((size_t)b * NLIN + (size_t)idx) * 4);
                }
            }
        }
    }
}

// ---- full post-process tail, run by the last-arriving CTA of the group ----
template<int LEVEL>
__device__ void finish_body(
    SharedState& sm, int b, int tid,
    const float* __restrict__ lb,
    const float* __restrict__ blk_raw,
    const float* __restrict__ lin_raw,
    const float* __restrict__ chr_raw,
    const float* __restrict__ tsz,
    float* __restrict__ out)
{
    constexpr int N = (LEVEL == 0) ? NBLK : NLIN;
    const int seg = LEVEL * B_IMGS + b;

    sm.fckey[tid] = 0ull;
    sm.fckey[tid + NT] = 0ull;
    if (tid < 32) sm.totals[tid] = 0;
    if (tid == 0) {
        sm.cnt_g = g_cnt[seg];
        g_cnt[seg] = 0;           // reset for next replay
        g_ticket[seg] = 0;
        sm.cnt = 0; sm.kcnt = 0; sm.argmax_idx = 0;
    }
    __syncthreads();
    const int cG = sm.cnt_g;

    int M;
    if (cG >= KSEL && cG <= FASTCAP) {
        // fast path: candidates already in global scratch (L2-hot)
        for (int c = tid; c < cG; c += NT) {
            uint2 cd = g_cand[seg * FASTCAP + c];
            sm.fckey[c] = sig_key(cd.x, (int)cd.y);
        }
        M = cG;
    } else {
        // cold fallback: exact bitwise top-KSEL search over full level
        unsigned int prefix = 0u;
        int cnt_cur = N;
        const float4* lb4 = (const float4*)lb;
        const int F4 = N / 4 / NT;
        for (int bit = 31; bit >= 0; --bit) {
            if (cnt_cur <= FASTCAP) break;
            unsigned int cand = prefix | (1u << bit);
            unsigned int c = 0;
            for (int r4 = 0; r4 < F4; ++r4) {
                float4 v = lb4[tid + r4 * NT];
                c += (fkey(v.x) >= cand) + (fkey(v.y) >= cand)
                   + (fkey(v.z) >= cand) + (fkey(v.w) >= cand);
            }
            c = __reduce_add_sync(0xFFFFFFFFu, c);
            if ((tid & 31) == 0 && c) atomicAdd(&sm.totals[bit], (int)c);
            __syncthreads();
            int tot = sm.totals[bit];
            if (tot >= KSEL) { prefix = cand; cnt_cur = tot; }
        }
        for (int r4 = 0; r4 < F4; ++r4) {
            float4 v = lb4[tid + r4 * NT];
            const int base = 4 * (tid + r4 * NT);
            unsigned int kk[4] = { fkey(v.x), fkey(v.y), fkey(v.z), fkey(v.w) };
#pragma unroll
            for (int c = 0; c < 4; ++c) {
                if (kk[c] >= prefix) {
                    int p = atomicAdd(&sm.cnt, 1);
                    if (p < FASTCAP) sm.scand[p] = make_uint2(kk[c], (unsigned int)(base + c));
                }
            }
        }
        __syncthreads();
        int cg = min(sm.cnt, FASTCAP);
        for (int c = tid; c < cg; c += NT) {
            uint2 cd = sm.scand[c];
            sm.fckey[c] = sig_key(cd.x, (int)cd.y);
        }
        M = cg;
    }
    __syncthreads();

    // ---- rank by composite key desc == (prob desc, index asc) ----
    for (int c = tid; c < M; c += NT) {
        const unsigned long long mk = sm.fckey[c];
        int rank = 0;
        const int Mp = (M + 3) & ~3;
        for (int j = 0; j < Mp; j += 4) {
            rank += (sm.fckey[j]     > mk) ? 1 : 0;
            rank += (sm.fckey[j + 1] > mk) ? 1 : 0;
            rank += (sm.fckey[j + 2] > mk) ? 1 : 0;
            rank += (sm.fckey[j + 3] > mk) ? 1 : 0;
        }
        if (rank < TOPK) {
            sm.sval[rank] = __uint_as_float((unsigned int)(mk >> 32));
            sm.sidx[rank] = (int)(~(unsigned int)(mk & 0xFFFFFFFFu));
        }
    }
    __syncthreads();

    const float hh = tsz[2 * b + 0];   // img_h
    const float ww = tsz[2 * b + 1];   // img_w

    // ---- char level: scattered ctrl-point gather over 400 tasks ----
    if (LEVEL == 2) {
        for (int t = tid; t < TOPK * 4; t += NT) {
            const int k = t >> 2, q = t & 3;
            const int si = sm.sidx[k];
            float4 v = ((const float4*)(chr_raw + ((size_t)b * NCHR + (size_t)si) * 16))[q];
            v.x *= hh; v.y *= ww; v.z *= hh; v.w *= ww;
            sm.sdat4[k][q] = v;
        }
        __syncthreads();
    }

    // ---- per-detection geometry ----
    if (tid < TOPK) {
        const int k  = tid;
        const int si = sm.sidx[k];
        float x1, y1, x2, y2;
        float4 p;

        if (LEVEL == 1) {
            p = ((const float4*)(blk_raw + ((size_t)b * NBLK + (size_t)(si >> 2)) * 4))[0];
        } else if (LEVEL == 2) {
            p = ((const float4*)(lin_raw + ((size_t)b * NLIN + (size_t)si) * 4))[0];
        }

        if (LEVEL == 2) {
            float ctrl[16];
#pragma unroll
            for (int q = 0; q < 4; ++q) {
                float4 v = sm.sdat4[k][q];
                ctrl[4 * q + 0] = v.x; ctrl[4 * q + 1] = v.y;
                ctrl[4 * q + 2] = v.z; ctrl[4 * q + 3] = v.w;
            }
            float mnx = 1e30f, mny = 1e30f, mxx = -1e30f, mxy = -1e30f;
#pragma unroll
            for (int s = 0; s < 10; ++s) {
                float t  = (float)s * (1.0f / 9.0f);
                float ti = 1.0f - t;
                float b0 = ti * ti * ti;
                float b1 = 3.0f * t * ti * ti;
                float b2 = 3.0f * t * t * ti;
                float b3 = t * t * t;
                float xt = b0 * ctrl[0] + b1 * ctrl[2]  + b2 * ctrl[4]  + b3 * ctrl[6];
                float yt = b0 * ctrl[1] + b1 * ctrl[3]  + b2 * ctrl[5]  + b3 * ctrl[7];
                float xb = b0 * ctrl[8] + b1 * ctrl[10] + b2 * ctrl[12] + b3 * ctrl[14];
                float yb = b0 * ctrl[9] + b1 * ctrl[11] + b2 * ctrl[13] + b3 * ctrl[15];
                mnx = fminf(mnx, fminf(xt, xb));
                mny = fminf(mny, fminf(yt, yb));
                mxx = fmaxf(mxx, fmaxf(xt, xb));
                mxy = fmaxf(mxy, fmaxf(yt, yb));
            }
            x1 = mnx; y1 = mny; x2 = mxx; y2 = mxy;
        } else {
            float4 v = (LEVEL == 0)
                ? ((const float4*)(blk_raw + ((size_t)b * NBLK + (size_t)si) * 4))[0]
                : ((const float4*)(lin_raw + ((size_t)b * NLIN + (size_t)si) * 4))[0];
            x1 = (v.x - 0.5f * v.z) * ww;
            y1 = (v.y - 0.5f * v.w) * hh;
            x2 = (v.x + 0.5f * v.z) * ww;
            y2 = (v.y + 0.5f * v.w) * hh;
            if (LEVEL == 0) {
                x1 = fminf(fmaxf(x1, 0.0f), ww);
                y1 = fminf(fmaxf(y1, 0.0f), hh);
                x2 = fminf(fmaxf(x2, 0.0f), ww);
                y2 = fminf(fmaxf(y2, 0.0f), hh);
            }
            float4 d; d.x = x1; d.y = y1; d.z = x2; d.w = y2;
            sm.sdat4[k][0] = d;
        }

        float4 bx; bx.x = x1; bx.y = y1; bx.z = x2; bx.w = y2;
        sm.sbox4[k] = bx;
        sm.sarea[k] = (x2 - x1) * (y2 - y1);

        bool kp   = sm.sval[k] > 0.1f;
        bool anyk = sm.sval[0] > 0.1f;
        if (!anyk) kp = (k == 0);
        sm.skeep[k] = kp ? 1 : 0;

        if (LEVEL > 0) {
            float px1 = (p.x - 0.5f * p.z) * ww;
            float py1 = (p.y - 0.5f * p.w) * hh;
            float px2 = (p.x + 0.5f * p.z) * ww;
            float py2 = (p.y + 0.5f * p.w) * hh;
            float ix1 = fmaxf(x1, px1);
            float iy1 = fmaxf(y1, py1);
            float ix2 = fminf(x2, px2);
            float iy2 = fminf(y2, py2);
            float inter = fmaxf(ix2 - ix1, 0.0f) * fmaxf(iy2 - iy1, 0.0f);
            float carea = (x2 - x1) * (y2 - y1);
            sm.sbelong[k] = inter / (carea + 1e-6f);
        }
    }
    __syncthreads();

    // ---- belong validity + fallback (lines / chars), parallel argmax ----
    if (LEVEL > 0) {
        const bool in = (tid < TOPK) && (sm.skeep[tid] != 0);
        const float bl = in ? sm.sbelong[tid] : 0.0f;
        int any_vk = __syncthreads_count(in && (bl > 0.6f));
        unsigned long long key = in
            ? (((unsigned long long)__float_as_uint(bl) << 32) | (unsigned int)(~(unsigned int)tid))
            : 0ull;
#pragma unroll
        for (int off = 16; off > 0; off >>= 1) {
            unsigned long long o = __shfl_down_sync(0xFFFFFFFFu, key, off);
            key = (o > key) ? o : key;
        }
        if ((tid & 31) == 0) sm.wkeys[tid >> 5] = key;
        __syncthreads();
        if (tid == 0) {
            unsigned long long best = 0ull;
#pragma unroll
            for (int w = 0; w < NT / 32; ++w) best = (sm.wkeys[w] > best) ? sm.wkeys[w] : best;
            sm.argmax_idx = (best == 0ull) ? 0 : (int)(~(unsigned int)(best & 0xFFFFFFFFu));
        }
        __syncthreads();
        if (tid < TOPK) {
            bool valid = sm.sbelong[tid] > 0.6f;
            if (any_vk == 0) valid = (tid == sm.argmax_idx);
            if (!valid) sm.skeep[tid] = 0;
        }
        __syncthreads();
    }

    // ---- keep ballot + compact kept-index list ----
    if (tid < 128) {
        bool kp = (tid < TOPK) && (sm.skeep[tid] != 0);
        unsigned int m = __ballot_sync(0xFFFFFFFFu, kp);
        if ((tid & 31) == 0) sm.keepw[tid >> 5] = m;
    }
    if (tid < TOPK && sm.skeep[tid]) {
        int p = atomicAdd(&sm.kcnt, 1);
        sm.klist[p] = tid;
    }
    __syncthreads();

    // ---- NMS adjacency: only rows for initially-kept boxes ----
    {
        const int warp = tid >> 5, lane = tid & 31;
        const int ntask = sm.kcnt * 4;
        for (int task = warp; task < ntask; task += NT / 32) {
            const int i = sm.klist[task >> 2], w = task & 3;
            unsigned int m = 0u;
            if (i < 32 * (w + 1)) {
                const int j = w * 32 + lane;
                bool pred = false;
                if (j < TOPK && j > i) {
                    float4 bi_ = sm.sbox4[i];
                    float4 bj_ = sm.sbox4[j];
                    float ix1 = fmaxf(bi_.x, bj_.x);
                    float iy1 = fmaxf(bi_.y, bj_.y);
                    float ix2 = fminf(bi_.z, bj_.z);
                    float iy2 = fminf(bi_.w, bj_.w);
                    float inter = fmaxf(ix2 - ix1, 0.0f) * fmaxf(iy2 - iy1, 0.0f);
                    pred = inter > 0.1f * (sm.sarea[i] + sm.sarea[j] - inter);
                }
                m = __ballot_sync(0xFFFFFFFFu, pred);
            }
            if (lane == 0) sm.adj[i][w] = m;
        }
    }
    __syncthreads();

    // ---- suppression scan: ffs-jump over still-kept boxes only ----
    if (tid == 0) {
        unsigned int kk0 = sm.keepw[0], kk1 = sm.keepw[1], kk2 = sm.keepw[2], kk3 = sm.keepw[3];
        const uint4* adj4 = (const uint4*)sm.adj;
#pragma unroll
        for (int w = 0; w < 4; ++w) {
            unsigned int cur = (w == 0) ? kk0 : (w == 1) ? kk1 : (w == 2) ? kk2 : kk3;
            unsigned int m = cur;
            while (m) {
                int bitp = __ffs(m) - 1;
                int i = 32 * w + bitp;
                uint4 a = adj4[i];
                kk0 &= ~a.x; kk1 &= ~a.y; kk2 &= ~a.z; kk3 &= ~a.w;
                cur = (w == 0) ? kk0 : (w == 1) ? kk1 : (w == 2) ? kk2 : kk3;
                m = cur & ((0xFFFFFFFFu << bitp) << 1);
            }
        }
        sm.keepw[0] = kk0; sm.keepw[1] = kk1; sm.keepw[2] = kk2; sm.keepw[3] = kk3;
    }
    __syncthreads();

    // ---- write outputs ----
    constexpr size_t data_off  = (LEVEL == 0) ? 0      : (LEVEL == 1) ? 38400 : 76800;
    constexpr size_t score_off = (LEVEL == 0) ? 25600  : (LEVEL == 1) ? 64000 : 179200;
    constexpr size_t keep_off  = (LEVEL == 0) ? 32000  : (LEVEL == 1) ? 70400 : 185600;
    const float4 z4 = make_float4(0.f, 0.f, 0.f, 0.f);

    if (LEVEL == 2) {
        float4* dp4 = (float4*)(out + data_off + (size_t)b * TOPK * 16);
        for (int t = tid; t < TOPK * 4; t += NT) {
            const int k = t >> 2, q = t & 3;
            bool kp = (sm.keepw[k >> 5] >> (k & 31)) & 1u;
            dp4[t] = kp ? sm.sdat4[k][q] : z4;
        }
    } else {
        float4* dp4 = (float4*)(out + data_off + (size_t)b * TOPK * 4);
        if (tid < TOPK) {
            bool kp = (sm.keepw[tid >> 5] >> (tid & 31)) & 1u;
            dp4[tid] = kp ? sm.sdat4[tid][0] : z4;
        }
    }
    if (tid < TOPK) {
        bool kp = (sm.keepw[tid >> 5] >> (tid & 31)) & 1u;
        out[score_off + (size_t)b * TOPK + tid] = kp ? sm.sval[tid] : 0.0f;
        out[keep_off  + (size_t)b * TOPK + tid] = kp ? 1.0f : 0.0f;
    }
}

__global__ void __launch_bounds__(NT)
postprocess_kernel(const float* __restrict__ blk_logit,
                   const float* __restrict__ lin_logit,
                   const float* __restrict__ chr_logit,
                   const float* __restrict__ blk_raw,
                   const float* __restrict__ lin_raw,
                   const float* __restrict__ chr_raw,
                   const float* __restrict__ tsz,
                   float* __restrict__ out)
{
    __shared__ SharedState sm;
    const int quarter = blockIdx.x;
    const int b       = blockIdx.y;
    const int level   = blockIdx.z;
    const int tid     = threadIdx.x;
    const int seg     = level * B_IMGS + b;

    const float* lb = (level == 0) ? blk_logit + (size_t)b * NBLK
                    : (level == 1) ? lin_logit + (size_t)b * NLIN
                                   : chr_logit + (size_t)b * NCHR;

    // phase 1: filter this CTA's quarter into global scratch
    if (level == 0)      filter_part<1, 0>(b, quarter, tid, seg, lb, blk_raw, lin_raw, chr_raw);
    else if (level == 1) filter_part<4, 1>(b, quarter, tid, seg, lb, blk_raw, lin_raw, chr_raw);
    else                 filter_part<4, 2>(b, quarter, tid, seg, lb, blk_raw, lin_raw, chr_raw);

    // phase 2: last CTA of the group finishes the segment
    __threadfence();
    __syncthreads();
    if (tid == 0) {
        int old = atomicAdd(&g_ticket[seg], 1);
        sm.is_last = (old == NQ - 1) ? 1 : 0;
    }
    __syncthreads();
    if (!sm.is_last) return;
    __threadfence();

    if (level == 0)      finish_body<0>(sm, b, tid, lb, blk_raw, lin_raw, chr_raw, tsz, out);
    else if (level == 1) finish_body<1>(sm, b, tid, lb, blk_raw, lin_raw, chr_raw, tsz, out);
    else                 finish_body<2>(sm, b, tid, lb, blk_raw, lin_raw, chr_raw, tsz, out);
}

extern "C" void kernel_launch(void* const* d_in, const int* in_sizes, int n_in,
                              void* d_out, int out_size) {
    (void)in_sizes; (void)n_in; (void)out_size;
    postprocess_kernel<<<dim3(NQ, B_IMGS, 3), NT>>>(
        (const float*)d_in[0],   // pred_block_logits
        (const float*)d_in[1],   // pred_line_logits
        (const float*)d_in[2],   // pred_char_logits
        (const float*)d_in[3],   // pred_block
        (const float*)d_in[4],   // pred_line
        (const float*)d_in[5],   // pred_char
        (const float*)d_in[6],   // target_sizes
        (float*)d_out);
}

// round 12
// speedup vs baseline: 2.2163x; 2.2163x over previous
#include <cuda_runtime.h>
#include <math.h>

#define B_IMGS   64
#define NBLK     4096
#define NLIN     16384
#define NCHR     16384
#define TOPK     100
#define KSEL     128
#define NT       512
#define FASTCAP  512
#define RAWCAP   384      // raw-preload slots (cand counts ~200-350; guarded fallback)

#define TH0 1.5f          // threshold guess, N=4096
#define TH1 2.25f         // threshold guess, N=16384

// Output layout (float32), reference return order (*blk, *lin, *chr):
//  blk_data [64,100,4]  @ 0       blk_scores @ 25600   blk_keep @ 32000
//  lin_data [64,100,4]  @ 38400   lin_scores @ 64000   lin_keep @ 70400
//  chr_data [64,100,16] @ 76800   chr_scores @ 179200  chr_keep @ 185600

union CandU { uint2 cd; unsigned long long key; };

struct __align__(16) SharedState {
    unsigned int adj[TOPK][4];
    float4 sdat4[TOPK][4];
    float4 sbox4[TOPK];
    float4 sraw[RAWCAP][4];     // preloaded candidate raw rows
    CandU  cand[FASTCAP];       // (key,idx) then overlaid by composite sig key
    float sval[TOPK];
    int   sidx[TOPK];
    int   sslot[TOPK];
    float sarea[TOPK];
    float sbelong[TOPK];
    int   skeep[TOPK];
    int   klist[TOPK];
    unsigned int keepw[4];
    int totals[32];
    int cnt;
    int kcnt;
};

__device__ __forceinline__ unsigned int fkey(float f) {
    unsigned int u = __float_as_uint(f);
    return u ^ (((unsigned int)((int)u >> 31)) | 0x80000000u);
}

__device__ __forceinline__ unsigned long long sig_key(unsigned int key, int idx) {
    unsigned int u = key ^ ((key & 0x80000000u) ? 0x80000000u : 0xFFFFFFFFu);
    float x = __uint_as_float(u);
    float prob = 1.0f / (1.0f + __expf(-x));
    return ((unsigned long long)__float_as_uint(prob) << 32)
           | (unsigned int)(~(unsigned int)idx);
}

template<int LOC, int LEVEL>
__device__ __forceinline__ void pp_body(
    SharedState& sm, int b, int tid,
    const float* __restrict__ lb,
    const float* __restrict__ blk_raw,
    const float* __restrict__ lin_raw,
    const float* __restrict__ chr_raw,
    const float* __restrict__ tsz,
    float* __restrict__ out)
{
    const int N = LOC * NT;
    constexpr float TH = (LEVEL == 0) ? TH0 : TH1;

    sm.cand[tid].key = 0ull;            // zero-pad for unrolled rank loop
    if (tid < 32) sm.totals[tid] = 0;
    if (tid == 0) { sm.cnt = 0; sm.kcnt = 0; }
    __syncthreads();

    // ---- streaming threshold filter ----
    {
        const float4* lb4 = (const float4*)lb;
#pragma unroll
        for (int r4 = 0; r4 < LOC / 4; ++r4) {
            float4 v = lb4[tid + r4 * NT];
            const int base = 4 * (tid + r4 * NT);
            float fv[4] = { v.x, v.y, v.z, v.w };
#pragma unroll
            for (int c = 0; c < 4; ++c) {
                if (fv[c] >= TH) {
                    int p = atomicAdd(&sm.cnt, 1);
                    if (p < FASTCAP)
                        sm.cand[p].cd = make_uint2(fkey(fv[c]), (unsigned int)(base + c));
                }
            }
        }
    }
    __syncthreads();
    const int cG = sm.cnt;

    int M;
    if (cG >= KSEL && cG <= FASTCAP) {
        M = cG;
    } else {
        // ---- cold fallback: exact bitwise search over global reads ----
        sm.cand[tid].key = 0ull;
        if (tid == 0) sm.cnt = 0;
        unsigned int prefix = 0u;
        int cnt_cur = N;
        const float4* lb4 = (const float4*)lb;
        for (int bit = 31; bit >= 0; --bit) {
            if (cnt_cur <= FASTCAP) break;
            unsigned int cand = prefix | (1u << bit);
            unsigned int c = 0;
            for (int r4 = 0; r4 < LOC / 4; ++r4) {
                float4 v = lb4[tid + r4 * NT];
                c += (fkey(v.x) >= cand) + (fkey(v.y) >= cand)
                   + (fkey(v.z) >= cand) + (fkey(v.w) >= cand);
            }
            c = __reduce_add_sync(0xFFFFFFFFu, c);
            if ((tid & 31) == 0 && c) atomicAdd(&sm.totals[bit], (int)c);
            __syncthreads();
            int tot = sm.totals[bit];
            if (tot >= KSEL) { prefix = cand; cnt_cur = tot; }
        }
        for (int r4 = 0; r4 < LOC / 4; ++r4) {
            float4 v = lb4[tid + r4 * NT];
            const int base = 4 * (tid + r4 * NT);
            unsigned int kk[4] = { fkey(v.x), fkey(v.y), fkey(v.z), fkey(v.w) };
#pragma unroll
            for (int c = 0; c < 4; ++c) {
                if (kk[c] >= prefix) {
                    int p = atomicAdd(&sm.cnt, 1);
                    if (p < FASTCAP)
                        sm.cand[p].cd = make_uint2(kk[c], (unsigned int)(base + c));
                }
            }
        }
        __syncthreads();
        M = min(sm.cnt, FASTCAP);
    }

    // ---- candidate stage: issue raw-row LDGs early, overlay sig key ----
    float4 r0, r1, r2, r3;
    const bool own = (tid < M);
    int myidx = 0;
    if (own) {
        uint2 cd = sm.cand[tid].cd;
        myidx = (int)cd.y;
        if (tid < RAWCAP) {
            if (LEVEL == 2) {
                const float4* rp = (const float4*)(chr_raw + ((size_t)b * NCHR + (size_t)myidx) * 16);
                r0 = rp[0]; r1 = rp[1]; r2 = rp[2]; r3 = rp[3];
            } else if (LEVEL == 1) {
                r0 = *(const float4*)(lin_raw + ((size_t)b * NLIN + (size_t)myidx) * 4);
            } else {
                r0 = *(const float4*)(blk_raw + ((size_t)b * NBLK + (size_t)myidx) * 4);
            }
        }
        sm.cand[tid].key = sig_key(cd.x, myidx);
    }
    __syncthreads();

    // ---- rank (hides the pending LDGs), then publish raws + rank results ----
    if (own) {
        const unsigned long long mk = sm.cand[tid].key;
        int rank = 0;
        const int Mp = (M + 3) & ~3;
        for (int j = 0; j < Mp; j += 4) {
            rank += (sm.cand[j].key     > mk) ? 1 : 0;
            rank += (sm.cand[j + 1].key > mk) ? 1 : 0;
            rank += (sm.cand[j + 2].key > mk) ? 1 : 0;
            rank += (sm.cand[j + 3].key > mk) ? 1 : 0;
        }
        if (tid < RAWCAP) {
            sm.sraw[tid][0] = r0;
            if (LEVEL == 2) { sm.sraw[tid][1] = r1; sm.sraw[tid][2] = r2; sm.sraw[tid][3] = r3; }
        }
        if (rank < TOPK) {
            sm.sval[rank]  = __uint_as_float((unsigned int)(mk >> 32));
            sm.sidx[rank]  = myidx;
            sm.sslot[rank] = tid;
        }
    }
    __syncthreads();

    const float hh = tsz[2 * b + 0];   // img_h
    const float ww = tsz[2 * b + 1];   // img_w

    // ---- per-detection geometry (raw rows from shared) ----
    if (tid < TOPK) {
        const int k  = tid;
        const int si = sm.sidx[k];
        const int c  = sm.sslot[k];
        float x1, y1, x2, y2;
        float4 p;

        if (LEVEL == 1) {
            p = *(const float4*)(blk_raw + ((size_t)b * NBLK + (size_t)(si >> 2)) * 4);
        } else if (LEVEL == 2) {
            p = *(const float4*)(lin_raw + ((size_t)b * NLIN + (size_t)si) * 4);
        }

        if (LEVEL == 2) {
            float4 q0, q1, q2, q3;
            if (c < RAWCAP) {
                q0 = sm.sraw[c][0]; q1 = sm.sraw[c][1]; q2 = sm.sraw[c][2]; q3 = sm.sraw[c][3];
            } else {
                const float4* rp = (const float4*)(chr_raw + ((size_t)b * NCHR + (size_t)si) * 16);
                q0 = rp[0]; q1 = rp[1]; q2 = rp[2]; q3 = rp[3];
            }
            float ctrl[16];
            float4 qq[4] = { q0, q1, q2, q3 };
#pragma unroll
            for (int q = 0; q < 4; ++q) {
                ctrl[4 * q + 0] = qq[q].x * hh;
                ctrl[4 * q + 1] = qq[q].y * ww;
                ctrl[4 * q + 2] = qq[q].z * hh;
                ctrl[4 * q + 3] = qq[q].w * ww;
                float4 d; d.x = ctrl[4*q+0]; d.y = ctrl[4*q+1]; d.z = ctrl[4*q+2]; d.w = ctrl[4*q+3];
                sm.sdat4[k][q] = d;
            }
            float mnx = 1e30f, mny = 1e30f, mxx = -1e30f, mxy = -1e30f;
#pragma unroll
            for (int s = 0; s < 10; ++s) {
                float t  = (float)s * (1.0f / 9.0f);
                float ti = 1.0f - t;
                float b0 = ti * ti * ti;
                float b1 = 3.0f * t * ti * ti;
                float b2 = 3.0f * t * t * ti;
                float b3 = t * t * t;
                float xt = b0 * ctrl[0] + b1 * ctrl[2]  + b2 * ctrl[4]  + b3 * ctrl[6];
                float yt = b0 * ctrl[1] + b1 * ctrl[3]  + b2 * ctrl[5]  + b3 * ctrl[7];
                float xb = b0 * ctrl[8] + b1 * ctrl[10] + b2 * ctrl[12] + b3 * ctrl[14];
                float yb = b0 * ctrl[9] + b1 * ctrl[11] + b2 * ctrl[13] + b3 * ctrl[15];
                mnx = fminf(mnx, fminf(xt, xb));
                mny = fminf(mny, fminf(yt, yb));
                mxx = fmaxf(mxx, fmaxf(xt, xb));
                mxy = fmaxf(mxy, fmaxf(yt, yb));
            }
            x1 = mnx; y1 = mny; x2 = mxx; y2 = mxy;
        } else {
            float4 v;
            if (c < RAWCAP) v = sm.sraw[c][0];
            else v = (LEVEL == 0)
                ? *(const float4*)(blk_raw + ((size_t)b * NBLK + (size_t)si) * 4)
                : *(const float4*)(lin_raw + ((size_t)b * NLIN + (size_t)si) * 4);
            x1 = (v.x - 0.5f * v.z) * ww;
            y1 = (v.y - 0.5f * v.w) * hh;
            x2 = (v.x + 0.5f * v.z) * ww;
            y2 = (v.y + 0.5f * v.w) * hh;
            if (LEVEL == 0) {
                x1 = fminf(fmaxf(x1, 0.0f), ww);
                y1 = fminf(fmaxf(y1, 0.0f), hh);
                x2 = fminf(fmaxf(x2, 0.0f), ww);
                y2 = fminf(fmaxf(y2, 0.0f), hh);
            }
            float4 d; d.x = x1; d.y = y1; d.z = x2; d.w = y2;
            sm.sdat4[k][0] = d;
        }

        float4 bx; bx.x = x1; bx.y = y1; bx.z = x2; bx.w = y2;
        sm.sbox4[k] = bx;
        sm.sarea[k] = (x2 - x1) * (y2 - y1);

        bool kp   = sm.sval[k] > 0.1f;
        bool anyk = sm.sval[0] > 0.1f;     // desc-sorted => any() == first > thr
        if (!anyk) kp = (k == 0);
        sm.skeep[k] = kp ? 1 : 0;

        if (LEVEL > 0) {
            float px1 = (p.x - 0.5f * p.z) * ww;
            float py1 = (p.y - 0.5f * p.w) * hh;
            float px2 = (p.x + 0.5f * p.z) * ww;
            float py2 = (p.y + 0.5f * p.w) * hh;
            float ix1 = fmaxf(x1, px1);
            float iy1 = fmaxf(y1, py1);
            float ix2 = fminf(x2, px2);
            float iy2 = fminf(y2, py2);
            float inter = fmaxf(ix2 - ix1, 0.0f) * fmaxf(iy2 - iy1, 0.0f);
            float carea = (x2 - x1) * (y2 - y1);
            sm.sbelong[k] = inter / (carea + 1e-6f);
        }
    }
    __syncthreads();

    // ---- warp-0 finalize: belong validity + fallback argmax + keep words + klist ----
    if (tid < 32) {
        const int lane = tid;
        unsigned int keepb[4], validb[4];
        unsigned long long best = 0ull;
#pragma unroll
        for (int w = 0; w < 4; ++w) {
            int k = w * 32 + lane;
            bool kp = (k < TOPK) && (sm.skeep[k] != 0);
            keepb[w] = __ballot_sync(0xFFFFFFFFu, kp);
            if (LEVEL > 0) {
                float bl = (k < TOPK) ? sm.sbelong[k] : 0.0f;
                validb[w] = __ballot_sync(0xFFFFFFFFu, bl > 0.6f);
                unsigned long long key = kp
                    ? (((unsigned long long)__float_as_uint(bl) << 32)
                       | (unsigned int)(~(unsigned int)k))
                    : 0ull;
                best = (key > best) ? key : best;
            }
        }
        if (LEVEL > 0) {
#pragma unroll
            for (int off = 16; off > 0; off >>= 1) {
                unsigned long long o = __shfl_xor_sync(0xFFFFFFFFu, best, off);
                best = (o > best) ? o : best;
            }
            bool any_vk = ((keepb[0] & validb[0]) | (keepb[1] & validb[1]) |
                           (keepb[2] & validb[2]) | (keepb[3] & validb[3])) != 0u;
            int am = (best == 0ull) ? 0 : (int)(~(unsigned int)(best & 0xFFFFFFFFu));
            if (!any_vk) {
#pragma unroll
                for (int w = 0; w < 4; ++w)
                    validb[w] = ((am >> 5) == w) ? (1u << (am & 31)) : 0u;
            }
#pragma unroll
            for (int w = 0; w < 4; ++w) keepb[w] &= validb[w];
        }
        int base = 0;
#pragma unroll
        for (int w = 0; w < 4; ++w) {
            unsigned int m = keepb[w];
            if (lane == 0) sm.keepw[w] = m;
            if ((m >> lane) & 1u) {
                int pos = base + __popc(m & ((1u << lane) - 1u));
                sm.klist[pos] = w * 32 + lane;
            }
            base += __popc(m);
        }
        if (lane == 0) sm.kcnt = base;
    }
    __syncthreads();

    // ---- NMS adjacency: only rows for kept boxes ----
    {
        const int warp = tid >> 5, lane = tid & 31;
        const int ntask = sm.kcnt * 4;
        for (int task = warp; task < ntask; task += NT / 32) {
            const int i = sm.klist[task >> 2], w = task & 3;
            unsigned int m = 0u;
            if (i < 32 * (w + 1)) {
                const int j = w * 32 + lane;
                bool pred = false;
                if (j < TOPK && j > i) {
                    float4 bi_ = sm.sbox4[i];
                    float4 bj_ = sm.sbox4[j];
                    float ix1 = fmaxf(bi_.x, bj_.x);
                    float iy1 = fmaxf(bi_.y, bj_.y);
                    float ix2 = fminf(bi_.z, bj_.z);
                    float iy2 = fminf(bi_.w, bj_.w);
                    float inter = fmaxf(ix2 - ix1, 0.0f) * fmaxf(iy2 - iy1, 0.0f);
                    pred = inter > 0.1f * (sm.sarea[i] + sm.sarea[j] - inter);
                }
                m = __ballot_sync(0xFFFFFFFFu, pred);
            }
            if (lane == 0) sm.adj[i][w] = m;
        }
    }
    __syncthreads();

    // ---- suppression scan: ffs-jump over still-kept boxes only ----
    if (tid == 0) {
        unsigned int kk0 = sm.keepw[0], kk1 = sm.keepw[1], kk2 = sm.keepw[2], kk3 = sm.keepw[3];
        const uint4* adj4 = (const uint4*)sm.adj;
#pragma unroll
        for (int w = 0; w < 4; ++w) {
            unsigned int cur = (w == 0) ? kk0 : (w == 1) ? kk1 : (w == 2) ? kk2 : kk3;
            unsigned int m = cur;
            while (m) {
                int bitp = __ffs(m) - 1;
                int i = 32 * w + bitp;
                uint4 a = adj4[i];
                kk0 &= ~a.x; kk1 &= ~a.y; kk2 &= ~a.z; kk3 &= ~a.w;
                cur = (w == 0) ? kk0 : (w == 1) ? kk1 : (w == 2) ? kk2 : kk3;
                m = cur & ((0xFFFFFFFFu << bitp) << 1);
            }
        }
        sm.keepw[0] = kk0; sm.keepw[1] = kk1; sm.keepw[2] = kk2; sm.keepw[3] = kk3;
    }
    __syncthreads();

    // ---- write outputs ----
    constexpr size_t data_off  = (LEVEL == 0) ? 0      : (LEVEL == 1) ? 38400 : 76800;
    constexpr size_t score_off = (LEVEL == 0) ? 25600  : (LEVEL == 1) ? 64000 : 179200;
    constexpr size_t keep_off  = (LEVEL == 0) ? 32000  : (LEVEL == 1) ? 70400 : 185600;
    const float4 z4 = make_float4(0.f, 0.f, 0.f, 0.f);

    if (LEVEL == 2) {
        float4* dp4 = (float4*)(out + data_off + (size_t)b * TOPK * 16);
        if (tid < TOPK * 4) {
            const int k = tid >> 2, q = tid & 3;
            bool kp = (sm.keepw[k >> 5] >> (k & 31)) & 1u;
            dp4[tid] = kp ? sm.sdat4[k][q] : z4;
        }
    } else {
        float4* dp4 = (float4*)(out + data_off + (size_t)b * TOPK * 4);
        if (tid < TOPK) {
            bool kp = (sm.keepw[tid >> 5] >> (tid & 31)) & 1u;
            dp4[tid] = kp ? sm.sdat4[tid][0] : z4;
        }
    }
    if (tid < TOPK) {
        bool kp = (sm.keepw[tid >> 5] >> (tid & 31)) & 1u;
        out[score_off + (size_t)b * TOPK + tid] = kp ? sm.sval[tid] : 0.0f;
        out[keep_off  + (size_t)b * TOPK + tid] = kp ? 1.0f : 0.0f;
    }
}

__global__ void __launch_bounds__(NT)
postprocess_kernel(const float* __restrict__ blk_logit,
                   const float* __restrict__ lin_logit,
                   const float* __restrict__ chr_logit,
                   const float* __restrict__ blk_raw,
                   const float* __restrict__ lin_raw,
                   const float* __restrict__ chr_raw,
                   const float* __restrict__ tsz,
                   float* __restrict__ out)
{
    __shared__ SharedState sm;
    const int b     = blockIdx.x;
    const int level = blockIdx.y;
    const int tid   = threadIdx.x;

    if (level == 0) {
        pp_body<8, 0>(sm, b, tid, blk_logit + (size_t)b * NBLK,
                      blk_raw, lin_raw, chr_raw, tsz, out);
    } else if (level == 1) {
        pp_body<32, 1>(sm, b, tid, lin_logit + (size_t)b * NLIN,
                       blk_raw, lin_raw, chr_raw, tsz, out);
    } else {
        pp_body<32, 2>(sm, b, tid, chr_logit + (size_t)b * NCHR,
                       blk_raw, lin_raw, chr_raw, tsz, out);
    }
}

extern "C" void kernel_launch(void* const* d_in, const int* in_sizes, int n_in,
                              void* d_out, int out_size) {
    (void)in_sizes; (void)n_in; (void)out_size;
    postprocess_kernel<<<dim3(B_IMGS, 3), NT>>>(
        (const float*)d_in[0],   // pred_block_logits
        (const float*)d_in[1],   // pred_line_logits
        (const float*)d_in[2],   // pred_char_logits
        (const float*)d_in[3],   // pred_block
        (const float*)d_in[4],   // pred_line
        (const float*)d_in[5],   // pred_char
        (const float*)d_in[6],   // target_sizes
        (float*)d_out);
}